// round 15
// baseline (speedup 1.0000x reference)
#include <cuda_runtime.h>
#include <cuda_fp16.h>
#include <cstdint>

// Problem constants
#define NN       8192
#define IN_DIM   256
#define NHEAD    4
#define HDIM     64
#define COLS     256   // NHEAD*HDIM

// attention tiling
#define TI   64                    // rows per block
#define TJ   64                    // j per chunk (K)
#define JS   8                     // j-splits
#define JCH  ((NN / JS) / TJ)      // 16 chunks per block

// smem byte offsets — 3-deep ring
#define OFF_B     0u               // 3 bufs x 32768 (256 c-rows x 64 j fp16, SW128)
#define OFF_EFS   98304u           // 3 bufs x 1024 ([h][plane][32 u32] E/F fp16 pairs)
#define SMEM_REQ  (101376u + 1024u)

// gemm smem: hsT 256*34 floats + Ws 64*256 floats
#define GROWS      32
#define G_HSTRIDE  34
#define GS_FLOATS  (IN_DIM * G_HSTRIDE + 64 * COLS)
#define GS_BYTES   (GS_FLOATS * 4)          // 100352

#define SMEM_SWZ(off) ((off) ^ (((off) >> 3) & 0x70u))

// ---------------- PTX helpers ----------------
__device__ __forceinline__ uint32_t smem_u32(const void* p) {
    uint32_t a;
    asm("{ .reg .u64 t; cvta.to.shared.u64 t, %1; cvt.u32.u64 %0, t; }" : "=r"(a) : "l"(p));
    return a;
}
#define PACK2(out, lo, hi) \
    asm("mov.b64 %0, {%1, %2};" : "=l"(out) : "f"(lo), "f"(hi))
#define UNPACK2(lo, hi, in) \
    asm("mov.b64 {%0, %1}, %2;" : "=f"(lo), "=f"(hi) : "l"(in))
#define FMA2(d, a, b, c) \
    asm("fma.rn.f32x2 %0, %1, %2, %3;" : "=l"(d) : "l"(a), "l"(b), "l"(c))
// pack two f32 -> f16x2 (lo in low half)
#define CVT_F16X2(r, lo, hi) \
    asm("cvt.rn.f16x2.f32 %0, %1, %2;" : "=r"(r) : "f"(hi), "f"(lo))
#define HMUL2(d, a, b) \
    asm("mul.rn.f16x2 %0, %1, %2;" : "=r"(d) : "r"(a), "r"(b))
#define HMAX2(d, a, b) \
    asm("max.f16x2 %0, %1, %2;" : "=r"(d) : "r"(a), "r"(b))
#define PRMT(d, a, sel) \
    asm("prmt.b32 %0, %1, %2, %3;" : "=r"(d) : "r"(a), "r"(0u), "n"(sel))

#define CP_ASYNC16(dst, src) \
    asm volatile("cp.async.cg.shared.global [%0], [%1], 16;" :: "r"(dst), "l"(src))
#define CP_COMMIT() asm volatile("cp.async.commit_group;" ::: "memory")
#define CP_WAIT(n)  asm volatile("cp.async.wait_group %0;" :: "n"(n) : "memory")

#define LDSM2(r0, r1, addr) \
    asm volatile("ldmatrix.sync.aligned.m8n8.x2.shared.b16 {%0,%1}, [%2];" \
        : "=r"(r0), "=r"(r1) : "r"(addr))

#define MMA16816(d, a0, a1, a2, a3, b0, b1) \
    asm volatile("mma.sync.aligned.m16n8k16.row.col.f32.f16.f16.f32 " \
        "{%0,%1,%2,%3}, {%4,%5,%6,%7}, {%8,%9}, {%0,%1,%2,%3};" \
        : "+f"((d)[0]), "+f"((d)[1]), "+f"((d)[2]), "+f"((d)[3]) \
        : "r"(a0), "r"(a1), "r"(a2), "r"(a3), "r"(b0), "r"(b1))

// ---------------- scratch globals ----------------
__device__ float    g_Wht[NN * COLS];            // Wh fp32 [n][c] (for scores)
__device__ __half   g_WTf16[COLS * NN];          // Wh^T fp16 [c][j]  (4 MB)
__device__ uint32_t g_S16[NN * NHEAD];           // {E1 fp16 low, F1 fp16 high}
__device__ __half   g_E2h[NHEAD * NN];           // e^{s2} fp16, [h][n]
__device__ __half   g_F2h[NHEAD * NN];           // e^{.2 s2} fp16, [h][n]
__device__ uint32_t g_adjS[(size_t)NN * 128 * 4];    // spread bitmask, 16 MB
__device__ float    g_outP[(size_t)JS * NN * COLS];  // 64 MB
__device__ float    g_denP[(size_t)JS * NN * NHEAD];

// ---------------------------------------------------------------------------
// Kernel 0: pack adj into SPREAD bitmask.
// Per (row, chunk64, tg): u32 with bit(s, t) at position 8t+4+s where
// j_local = 16s + tg*2 + {0,1,8,9}[t]. One warp per row; ballot per 32 j.
// ---------------------------------------------------------------------------
__global__ __launch_bounds__(256) void k_pack(const int* __restrict__ adj)
{
    const int row  = blockIdx.x * 8 + (threadIdx.x >> 5);
    const int lane = threadIdx.x & 31;
    const int* rp = adj + (size_t)row * NN;
    uint32_t* op = g_adjS + (size_t)row * 512;
#pragma unroll 2
    for (int c = 0; c < 128; c++) {
        int v0 = rp[c * 64 + lane];
        int v1 = rp[c * 64 + 32 + lane];
        uint32_t lo = __ballot_sync(0xFFFFFFFFu, v0 != 0);
        uint32_t hi = __ballot_sync(0xFFFFFFFFu, v1 != 0);
        if (lane < 4) {
            uint32_t l = lo >> (lane * 2);
            uint32_t hh = hi >> (lane * 2);
            uint32_t o = 0;
            o |= (l & 0x1u) << 4;          // s0 t0 -> 4
            o |= (l & 0x2u) << 11;         // s0 t1 -> 12
            o |= (l & 0x100u) << 12;       // s0 t2 -> 20
            o |= (l & 0x200u) << 19;       // s0 t3 -> 28
            o |= (l >> 11) & 0x20u;        // s1 t0 -> 5
            o |= (l & 0x20000u) >> 4;      // s1 t1 -> 13
            o |= (l & 0x1000000u) >> 3;    // s1 t2 -> 21
            o |= (l & 0x2000000u) << 4;    // s1 t3 -> 29
            o |= (hh & 0x1u) << 6;         // s2 t0 -> 6
            o |= (hh & 0x2u) << 13;        // s2 t1 -> 14
            o |= (hh & 0x100u) << 14;      // s2 t2 -> 22
            o |= (hh & 0x200u) << 21;      // s2 t3 -> 30
            o |= (hh >> 9) & 0x80u;        // s3 t0 -> 7
            o |= (hh & 0x20000u) >> 2;     // s3 t1 -> 15
            o |= (hh & 0x1000000u) >> 1;   // s3 t2 -> 23
            o |= (hh & 0x2000000u) << 6;   // s3 t3 -> 31
            op[c * 4 + lane] = o;
        }
    }
}

// ---------------------------------------------------------------------------
// Kernel 1: Wh = h @ W ; also emit fp16 Wh^T plane.
// 32 rows/block; W staged through smem in 4 k-tiles of 64 (coalesced LDG,
// conflict-free stride-1 LDS) — removes the 256B-strided W LDG.32 stream.
// ---------------------------------------------------------------------------
__global__ __launch_bounds__(256) void k_gemm(const float* __restrict__ hmat,
                                              const float* __restrict__ W)
{
    extern __shared__ __align__(16) float gsm[];
    float* hsT = gsm;                       // [k][row] stride G_HSTRIDE
    float* Ws  = gsm + IN_DIM * G_HSTRIDE;  // [kk][c]  64 x 256

    const int n0 = blockIdx.x * GROWS;
    const int t  = threadIdx.x;

    // stage h rows transposed: 32 rows x 256 k = 2048 float4
    for (int q = t; q < GROWS * 64; q += 256) {
        int row = q >> 6, kq = q & 63;
        float4 v = *(const float4*)(hmat + (n0 + row) * IN_DIM + kq * 4);
        hsT[(kq * 4 + 0) * G_HSTRIDE + row] = v.x;
        hsT[(kq * 4 + 1) * G_HSTRIDE + row] = v.y;
        hsT[(kq * 4 + 2) * G_HSTRIDE + row] = v.z;
        hsT[(kq * 4 + 3) * G_HSTRIDE + row] = v.w;
    }

    const int c = t;
    unsigned long long acc[16];
#pragma unroll
    for (int rp = 0; rp < 16; rp++) acc[rp] = 0ull;

    for (int kt = 0; kt < 4; kt++) {
        __syncthreads();
        // stage W k-tile: 64 k x 256 c = 4096 float4, coalesced
#pragma unroll
        for (int v4 = 0; v4 < 16; v4++) {
            int q = v4 * 256 + t;
            int kk = q >> 6, c4 = q & 63;
            int head = c4 >> 4, d4 = c4 & 15;
            float4 v = *(const float4*)(W + head * (IN_DIM * HDIM)
                                          + (kt * 64 + kk) * HDIM + d4 * 4);
            *(float4*)(Ws + kk * COLS + c4 * 4) = v;
        }
        __syncthreads();

#pragma unroll 4
        for (int kk = 0; kk < 64; kk++) {
            const int k = kt * 64 + kk;
            float wv = Ws[kk * COLS + c];
            unsigned long long ws;
            PACK2(ws, wv, wv);
#pragma unroll
            for (int rp = 0; rp < 16; rp++) {
                unsigned long long hv =
                    *(const unsigned long long*)&hsT[k * G_HSTRIDE + rp * 2];
                FMA2(acc[rp], hv, ws, acc[rp]);
            }
        }
    }

    float val[32];
#pragma unroll
    for (int rp = 0; rp < 16; rp++) {
        UNPACK2(val[2 * rp], val[2 * rp + 1], acc[rp]);
        g_Wht[(n0 + 2 * rp + 0) * COLS + c] = val[2 * rp];
        g_Wht[(n0 + 2 * rp + 1) * COLS + c] = val[2 * rp + 1];
    }
    uint32_t hp[16];
#pragma unroll
    for (int q = 0; q < 16; q++) CVT_F16X2(hp[q], val[2 * q], val[2 * q + 1]);
    uint4* pd = (uint4*)(g_WTf16 + (size_t)c * NN + n0);
    pd[0] = make_uint4(hp[0],  hp[1],  hp[2],  hp[3]);
    pd[1] = make_uint4(hp[4],  hp[5],  hp[6],  hp[7]);
    pd[2] = make_uint4(hp[8],  hp[9],  hp[10], hp[11]);
    pd[3] = make_uint4(hp[12], hp[13], hp[14], hp[15]);
}

// ---------------------------------------------------------------------------
// Kernel 1b: scores + exp precompute (fp16 E/F)
// ---------------------------------------------------------------------------
__global__ __launch_bounds__(256) void k_scores(const float* __restrict__ a)
{
    const int gw   = (blockIdx.x * blockDim.x + threadIdx.x) >> 5;
    const int lane = threadIdx.x & 31;
    const int n = gw >> 2, head = gw & 3;

    float2 wv = *(const float2*)(g_Wht + n * COLS + head * HDIM + lane * 2);
    float a1x = a[lane * 2],      a1y = a[lane * 2 + 1];
    float a2x = a[64 + lane * 2], a2y = a[64 + lane * 2 + 1];
    float p1 = wv.x * a1x + wv.y * a1y;
    float p2 = wv.x * a2x + wv.y * a2y;
#pragma unroll
    for (int off = 16; off > 0; off >>= 1) {
        p1 += __shfl_xor_sync(0xFFFFFFFFu, p1, off);
        p2 += __shfl_xor_sync(0xFFFFFFFFu, p2, off);
    }
    if (lane == 0) {
        __half e1 = __float2half(expf(p1));
        __half f1 = __float2half(expf(0.2f * p1));
        uint32_t e1b, f1b;
        memcpy(&e1b, &e1, 2); e1b &= 0xFFFFu;
        memcpy(&f1b, &f1, 2); f1b &= 0xFFFFu;
        g_S16[n * NHEAD + head] = e1b | (f1b << 16);
        g_E2h[head * NN + n] = __float2half(expf(p2));
        g_F2h[head * NN + n] = __float2half(expf(0.2f * p2));
    }
}

// ---------------------------------------------------------------------------
// Kernel 2: HMMA attention aggregation. grid = (NN/TI)*JS = 1024, 256 thr,
// 2 blocks/SM. Warp = 32 rows x 1 head. fp16-native weight phase.
// Per k-step: ALL loads (LDS + 8x LDSM2) issued first, amt chain computed
// under their latency, MMAs last with both operands ready.
// ---------------------------------------------------------------------------
__global__ __launch_bounds__(256, 2) void k_attn()
{
    extern __shared__ __align__(16) char dsm[];
    const uint32_t sb = smem_u32(dsm);
    const uint32_t ab = (sb + 1023u) & ~1023u;
    char* abp = dsm + (ab - sb);

    const int t    = threadIdx.x;
    const int wid  = t >> 5;
    const int lane = t & 31;
    const int g    = lane >> 2;
    const int tg   = lane & 3;
    const int rg   = wid >> 2;         // rowgroup 0..1 (32 rows each)
    const int h    = wid & 3;          // head
    const int bx = blockIdx.x;
    const int js    = bx & (JS - 1);
    const int itile = bx >> 3;         // JS = 8
    const int i0     = itile * TI;
    const int j0base = js * (NN / JS);

    const int rbase = i0 + rg * 32 + g;    // rows rbase + {0,8,16,24}
    const uint32_t ONES2 = 0x3C003C00u;

    // per-row {E1,E1} / {F1,F1} f16x2 + spread-adj base ptrs
    uint32_t s1E[4], s1F[4];
    const uint32_t* ap[4];
#pragma unroll
    for (int ri = 0; ri < 4; ri++) {
        const int row = rbase + ri * 8;
        uint32_t sv = g_S16[row * NHEAD + h];
        PRMT(s1E[ri], sv, 0x1010);    // {E1, E1}
        PRMT(s1F[ri], sv, 0x3232);    // {F1, F1}
        ap[ri] = g_adjS + ((size_t)row * 128 + (j0base >> 6)) * 4 + tg;
    }

    auto stage = [&](int buf, int j0) {
#pragma unroll
        for (int v = 0; v < 8; v++) {
            int idx = v * 256 + t;
            int row = idx >> 3, u = idx & 7;
            const __half* src = g_WTf16 + (size_t)row * NN + j0 + u * 8;
            uint32_t dst = ab + OFF_B + buf * 32768 + SMEM_SWZ((uint32_t)(row * 128 + u * 16));
            CP_ASYNC16(dst, src);
        }
        if (t < 64) {
            int hh = t >> 4, plane = (t >> 3) & 1, gn = t & 7;
            const __half* src = (plane ? g_F2h : g_E2h) + (size_t)hh * NN + j0 + gn * 8;
            uint32_t dst = ab + OFF_EFS + buf * 1024 + (uint32_t)(hh * 256 + plane * 128 + gn * 16);
            CP_ASYNC16(dst, src);
        }
    };

    stage(0, j0base);
    CP_COMMIT();
    stage(1, j0base + TJ);
    CP_COMMIT();

    float acc[2][8][4];
#pragma unroll
    for (int mt = 0; mt < 2; mt++)
#pragma unroll
        for (int nt = 0; nt < 8; nt++)
#pragma unroll
            for (int q = 0; q < 4; q++) acc[mt][nt][q] = 0.0f;
    float accd[2][4];
#pragma unroll
    for (int mt = 0; mt < 2; mt++)
#pragma unroll
        for (int q = 0; q < 4; q++) accd[mt][q] = 0.0f;

    for (int ch = 0; ch < JCH; ch++) {
        const int buf = ch % 3;
        const int j0  = j0base + ch * TJ;

        // spread adj words for this chunk (4 rows, L2-resident, read once)
        uint32_t aw[4];
#pragma unroll
        for (int ri = 0; ri < 4; ri++) aw[ri] = ap[ri][ch * 4];

        if (ch < JCH - 1) CP_WAIT(1); else CP_WAIT(0);
        __syncthreads();

        if (ch + 2 < JCH) {
            stage((ch + 2) % 3, j0 + 2 * TJ);
            CP_COMMIT();
        }

        const uint32_t Eoff = OFF_EFS + buf * 1024 + (uint32_t)h * 256;
        const uint32_t Bb = ab + OFF_B + buf * 32768;
        const int r_c = lane & 7;
        const int jo2 = ((lane >> 3) & 1) * 8;

#pragma unroll
        for (int sp = 0; sp < 2; sp++) {
#pragma unroll
            for (int k2 = 0; k2 < 2; k2++) {
                const int s = sp * 2 + k2;

                // ---- phase 1: issue ALL loads for this k-step ----
                const uint32_t eb = Eoff + (uint32_t)(s * 8 + tg) * 4;
                uint32_t e01 = *(const uint32_t*)(abp + eb);
                uint32_t e89 = *(const uint32_t*)(abp + eb + 16);
                uint32_t f01 = *(const uint32_t*)(abp + eb + 128);
                uint32_t f89 = *(const uint32_t*)(abp + eb + 144);

                uint32_t bfr[8][2];
#pragma unroll
                for (int nt = 0; nt < 8; nt++) {
                    uint32_t addr = Bb + (uint32_t)(h * 8192)
                        + SMEM_SWZ((uint32_t)((nt * 8 + r_c) * 128
                                              + (sp * 32 + k2 * 16 + jo2) * 2));
                    LDSM2(bfr[nt][0], bfr[nt][1], addr);
                }

                // ---- phase 2: amt chain (executes under load latency) ----
                uint32_t amt[2][4];
#pragma unroll
                for (int ri = 0; ri < 4; ri++) {
                    uint32_t xs = aw[ri] << (3 - s);
                    uint32_t m01, m89;
                    PRMT(m01, xs, 0x9988);
                    PRMT(m89, xs, 0xBBAA);
                    uint32_t t1, t2, w01, w89;
                    HMUL2(t1, s1E[ri], e01);
                    HMUL2(t2, s1F[ri], f01);
                    HMAX2(w01, t1, t2);
                    HMUL2(t1, s1E[ri], e89);
                    HMUL2(t2, s1F[ri], f89);
                    HMAX2(w89, t1, t2);
                    amt[ri >> 1][ri & 1]       = w01 & m01;
                    amt[ri >> 1][(ri & 1) + 2] = w89 & m89;
                }

                // ---- phase 3: MMAs (operands ready) ----
                MMA16816(accd[0], amt[0][0], amt[0][1], amt[0][2], amt[0][3], ONES2, ONES2);
                MMA16816(accd[1], amt[1][0], amt[1][1], amt[1][2], amt[1][3], ONES2, ONES2);
#pragma unroll
                for (int nt = 0; nt < 8; nt++)
#pragma unroll
                    for (int mt = 0; mt < 2; mt++)
                        MMA16816(acc[mt][nt],
                                 amt[mt][0], amt[mt][1], amt[mt][2], amt[mt][3],
                                 bfr[nt][0], bfr[nt][1]);
            }
        }
    }

    // ---- epilogue ----
    if (tg == 0) {
#pragma unroll
        for (int ri = 0; ri < 4; ri++)
            g_denP[((size_t)js * NN + rbase + ri * 8) * NHEAD + h] =
                accd[ri >> 1][(ri & 1) * 2];
    }
#pragma unroll
    for (int mt = 0; mt < 2; mt++) {
        const size_t r0 = (size_t)js * NN + rbase + mt * 16;
#pragma unroll
        for (int nt = 0; nt < 8; nt++) {
            const int c0 = h * 64 + nt * 8 + tg * 2;
            *(float2*)(g_outP + r0 * COLS + c0) =
                make_float2(acc[mt][nt][0], acc[mt][nt][1]);
            *(float2*)(g_outP + (r0 + 8) * COLS + c0) =
                make_float2(acc[mt][nt][2], acc[mt][nt][3]);
        }
    }
}

// ---------------------------------------------------------------------------
// Kernel 3: combine j-split partials
// ---------------------------------------------------------------------------
__global__ __launch_bounds__(256) void k_comb(float* __restrict__ out)
{
    const int idx = blockIdx.x * 256 + threadIdx.x;   // float4 index over NN*64
    const int i  = idx >> 6;
    const int c4 = idx & 63;
    const int h  = c4 >> 4;

    float4 s = make_float4(0.f, 0.f, 0.f, 0.f);
    float d = 0.f;
#pragma unroll
    for (int js = 0; js < JS; js++) {
        float4 p = ((const float4*)g_outP)[((size_t)js * NN + i) * 64 + c4];
        s.x += p.x; s.y += p.y; s.z += p.z; s.w += p.w;
        d += g_denP[((size_t)js * NN + i) * NHEAD + h];
    }
    float inv = 1.0f / d;
    ((float4*)out)[idx] = make_float4(s.x * inv, s.y * inv, s.z * inv, s.w * inv);
}

// ---------------------------------------------------------------------------
extern "C" void kernel_launch(void* const* d_in, const int* in_sizes, int n_in,
                              void* d_out, int out_size)
{
    const float* hmat = (const float*)d_in[0];   // [8192, 256] f32
    const int*   adj  = (const int*)  d_in[1];   // [8192, 8192] i32
    const float* W    = (const float*)d_in[2];   // [4, 256, 64] f32
    const float* a    = (const float*)d_in[3];   // [128, 1] f32
    float* out = (float*)d_out;                  // [8192, 256] f32

    cudaFuncSetAttribute(k_attn, cudaFuncAttributeMaxDynamicSharedMemorySize, SMEM_REQ);
    cudaFuncSetAttribute(k_gemm, cudaFuncAttributeMaxDynamicSharedMemorySize, GS_BYTES);

    k_pack  <<<NN / 8, 256>>>(adj);
    k_gemm  <<<NN / GROWS, 256, GS_BYTES>>>(hmat, W);
    k_scores<<<(NN * NHEAD) / 8, 256>>>(a);
    k_attn  <<<(NN / TI) * JS, 256, SMEM_REQ>>>();
    k_comb  <<<(NN * 64) / 256, 256>>>(out);
}

// round 16
// speedup vs baseline: 1.0794x; 1.0794x over previous
#include <cuda_runtime.h>
#include <cuda_fp16.h>
#include <cstdint>

// Problem constants
#define NN       8192
#define IN_DIM   256
#define NHEAD    4
#define HDIM     64
#define COLS     256   // NHEAD*HDIM

// attention tiling
#define TI   64                    // rows per block
#define TJ   64                    // j per chunk (K)
#define JS   8                     // j-splits
#define JCH  ((NN / JS) / TJ)      // 16 chunks per block

// smem byte offsets — 3-deep ring
#define OFF_B     0u               // 3 bufs x 32768 (256 c-rows x 64 j fp16, SW128)
#define OFF_EFS   98304u           // 3 bufs x 1024 ([h][plane][32 u32] E/F fp16 pairs)
#define SMEM_REQ  (101376u + 1024u)

#define SMEM_SWZ(off) ((off) ^ (((off) >> 3) & 0x70u))

// ---------------- PTX helpers ----------------
__device__ __forceinline__ uint32_t smem_u32(const void* p) {
    uint32_t a;
    asm("{ .reg .u64 t; cvta.to.shared.u64 t, %1; cvt.u32.u64 %0, t; }" : "=r"(a) : "l"(p));
    return a;
}
#define PACK2(out, lo, hi) \
    asm("mov.b64 %0, {%1, %2};" : "=l"(out) : "f"(lo), "f"(hi))
#define UNPACK2(lo, hi, in) \
    asm("mov.b64 {%0, %1}, %2;" : "=f"(lo), "=f"(hi) : "l"(in))
#define FMA2(d, a, b, c) \
    asm("fma.rn.f32x2 %0, %1, %2, %3;" : "=l"(d) : "l"(a), "l"(b), "l"(c))
// pack two f32 -> f16x2 (lo in low half)
#define CVT_F16X2(r, lo, hi) \
    asm("cvt.rn.f16x2.f32 %0, %1, %2;" : "=r"(r) : "f"(hi), "f"(lo))
#define HMUL2(d, a, b) \
    asm("mul.rn.f16x2 %0, %1, %2;" : "=r"(d) : "r"(a), "r"(b))
#define HMAX2(d, a, b) \
    asm("max.f16x2 %0, %1, %2;" : "=r"(d) : "r"(a), "r"(b))
#define PRMT(d, a, sel) \
    asm("prmt.b32 %0, %1, %2, %3;" : "=r"(d) : "r"(a), "r"(0u), "n"(sel))

#define CP_ASYNC16(dst, src) \
    asm volatile("cp.async.cg.shared.global [%0], [%1], 16;" :: "r"(dst), "l"(src))
#define CP_COMMIT() asm volatile("cp.async.commit_group;" ::: "memory")
#define CP_WAIT(n)  asm volatile("cp.async.wait_group %0;" :: "n"(n) : "memory")

#define LDSM2(r0, r1, addr) \
    asm volatile("ldmatrix.sync.aligned.m8n8.x2.shared.b16 {%0,%1}, [%2];" \
        : "=r"(r0), "=r"(r1) : "r"(addr))

#define MMA16816(d, a0, a1, a2, a3, b0, b1) \
    asm volatile("mma.sync.aligned.m16n8k16.row.col.f32.f16.f16.f32 " \
        "{%0,%1,%2,%3}, {%4,%5,%6,%7}, {%8,%9}, {%0,%1,%2,%3};" \
        : "+f"((d)[0]), "+f"((d)[1]), "+f"((d)[2]), "+f"((d)[3]) \
        : "r"(a0), "r"(a1), "r"(a2), "r"(a3), "r"(b0), "r"(b1))

// ---------------- scratch globals ----------------
__device__ float    g_Wht[NN * COLS];            // Wh fp32 [n][c] (for scores)
__device__ __half   g_WTf16[COLS * NN];          // Wh^T fp16 [c][j]  (4 MB)
__device__ uint32_t g_S16[NN * NHEAD];           // {E1 fp16 low, F1 fp16 high}
__device__ __half   g_E2h[NHEAD * NN];           // e^{s2} fp16, [h][n]
__device__ __half   g_F2h[NHEAD * NN];           // e^{.2 s2} fp16, [h][n]
__device__ uint32_t g_adjS[(size_t)NN * 128 * 4];    // spread bitmask, 16 MB
__device__ float    g_outP[(size_t)JS * NN * COLS];  // 64 MB
__device__ float    g_denP[(size_t)JS * NN * NHEAD];

// ---------------------------------------------------------------------------
// Kernel A: fused pack + gemm. grid = 1536. bx%3==0 -> gemm (512 blocks),
// else -> pack (1024 blocks). DRAM-bound pack blocks and issue-bound gemm
// blocks co-reside on every SM, overlapping their bottlenecks.
// ---------------------------------------------------------------------------
__global__ __launch_bounds__(256) void k_pg(const int* __restrict__ adj,
                                            const float* __restrict__ hmat,
                                            const float* __restrict__ W)
{
    __shared__ __align__(16) float hsT[IN_DIM][18];
    const int bx = blockIdx.x;
    const int t  = threadIdx.x;

    if (bx % 3 != 0) {
        // ---- pack role: spread bitmask ----
        const int pack_idx = bx - bx / 3 - 1;       // 0..1023
        const int row  = pack_idx * 8 + (t >> 5);
        const int lane = t & 31;
        const int* rp = adj + (size_t)row * NN;
        uint32_t* op = g_adjS + (size_t)row * 512;
#pragma unroll 2
        for (int c = 0; c < 128; c++) {
            int v0 = rp[c * 64 + lane];
            int v1 = rp[c * 64 + 32 + lane];
            uint32_t lo = __ballot_sync(0xFFFFFFFFu, v0 != 0);
            uint32_t hi = __ballot_sync(0xFFFFFFFFu, v1 != 0);
            if (lane < 4) {
                uint32_t l = lo >> (lane * 2);
                uint32_t hh = hi >> (lane * 2);
                uint32_t o = 0;
                o |= (l & 0x1u) << 4;          // s0 t0 -> 4
                o |= (l & 0x2u) << 11;         // s0 t1 -> 12
                o |= (l & 0x100u) << 12;       // s0 t2 -> 20
                o |= (l & 0x200u) << 19;       // s0 t3 -> 28
                o |= (l >> 11) & 0x20u;        // s1 t0 -> 5
                o |= (l & 0x20000u) >> 4;      // s1 t1 -> 13
                o |= (l & 0x1000000u) >> 3;    // s1 t2 -> 21
                o |= (l & 0x2000000u) << 4;    // s1 t3 -> 29
                o |= (hh & 0x1u) << 6;         // s2 t0 -> 6
                o |= (hh & 0x2u) << 13;        // s2 t1 -> 14
                o |= (hh & 0x100u) << 14;      // s2 t2 -> 22
                o |= (hh & 0x200u) << 21;      // s2 t3 -> 30
                o |= (hh >> 9) & 0x80u;        // s3 t0 -> 7
                o |= (hh & 0x20000u) >> 2;     // s3 t1 -> 15
                o |= (hh & 0x1000000u) >> 1;   // s3 t2 -> 23
                o |= (hh & 0x2000000u) << 6;   // s3 t3 -> 31
                op[c * 4 + lane] = o;
            }
        }
        return;
    }

    // ---- gemm role: Wh = h @ W, emit fp32 Wh and fp16 Wh^T ----
    const int n0 = (bx / 3) * 16;

    for (int q = t; q < 1024; q += 256) {
        int row = q >> 6, kq = q & 63;
        float4 v = *(const float4*)(hmat + (n0 + row) * IN_DIM + kq * 4);
        hsT[kq * 4 + 0][row] = v.x;
        hsT[kq * 4 + 1][row] = v.y;
        hsT[kq * 4 + 2][row] = v.z;
        hsT[kq * 4 + 3][row] = v.w;
    }
    __syncthreads();

    const int c = t;
    const int head = c >> 6, d = c & 63;
    const float* Wp = W + head * (IN_DIM * HDIM) + d;

    unsigned long long acc[8];
#pragma unroll
    for (int rp = 0; rp < 8; rp++) acc[rp] = 0ull;

#pragma unroll 4
    for (int k = 0; k < IN_DIM; k++) {
        float wv = Wp[k * HDIM];
        unsigned long long ws;
        PACK2(ws, wv, wv);
#pragma unroll
        for (int rp = 0; rp < 8; rp++) {
            unsigned long long hv = *(const unsigned long long*)&hsT[k][rp * 2];
            FMA2(acc[rp], hv, ws, acc[rp]);
        }
    }

    float val[16];
#pragma unroll
    for (int rp = 0; rp < 8; rp++) {
        UNPACK2(val[2 * rp], val[2 * rp + 1], acc[rp]);
        g_Wht[(n0 + 2 * rp + 0) * COLS + c] = val[2 * rp];
        g_Wht[(n0 + 2 * rp + 1) * COLS + c] = val[2 * rp + 1];
    }
    uint32_t hp[8];
#pragma unroll
    for (int q = 0; q < 8; q++) CVT_F16X2(hp[q], val[2 * q], val[2 * q + 1]);
    uint4* pd = (uint4*)(g_WTf16 + (size_t)c * NN + n0);
    pd[0] = make_uint4(hp[0], hp[1], hp[2], hp[3]);
    pd[1] = make_uint4(hp[4], hp[5], hp[6], hp[7]);
}

// ---------------------------------------------------------------------------
// Kernel 1b: scores + exp precompute (fp16 E/F)
// ---------------------------------------------------------------------------
__global__ __launch_bounds__(256) void k_scores(const float* __restrict__ a)
{
    const int gw   = (blockIdx.x * blockDim.x + threadIdx.x) >> 5;
    const int lane = threadIdx.x & 31;
    const int n = gw >> 2, head = gw & 3;

    float2 wv = *(const float2*)(g_Wht + n * COLS + head * HDIM + lane * 2);
    float a1x = a[lane * 2],      a1y = a[lane * 2 + 1];
    float a2x = a[64 + lane * 2], a2y = a[64 + lane * 2 + 1];
    float p1 = wv.x * a1x + wv.y * a1y;
    float p2 = wv.x * a2x + wv.y * a2y;
#pragma unroll
    for (int off = 16; off > 0; off >>= 1) {
        p1 += __shfl_xor_sync(0xFFFFFFFFu, p1, off);
        p2 += __shfl_xor_sync(0xFFFFFFFFu, p2, off);
    }
    if (lane == 0) {
        __half e1 = __float2half(expf(p1));
        __half f1 = __float2half(expf(0.2f * p1));
        uint32_t e1b, f1b;
        memcpy(&e1b, &e1, 2); e1b &= 0xFFFFu;
        memcpy(&f1b, &f1, 2); f1b &= 0xFFFFu;
        g_S16[n * NHEAD + head] = e1b | (f1b << 16);
        g_E2h[head * NN + n] = __float2half(expf(p2));
        g_F2h[head * NN + n] = __float2half(expf(0.2f * p2));
    }
}

// ---------------------------------------------------------------------------
// Kernel 2: HMMA attention aggregation. grid = (NN/TI)*JS = 1024, 256 thr,
// 2 blocks/SM. Warp = 32 rows x 1 head. fp16-native weight phase.
// Per k-step: ALL loads (LDS + 8x LDSM2) issued first, amt chain computed
// under their latency, MMAs last with both operands ready.
// ---------------------------------------------------------------------------
__global__ __launch_bounds__(256, 2) void k_attn()
{
    extern __shared__ __align__(16) char dsm[];
    const uint32_t sb = smem_u32(dsm);
    const uint32_t ab = (sb + 1023u) & ~1023u;
    char* abp = dsm + (ab - sb);

    const int t    = threadIdx.x;
    const int wid  = t >> 5;
    const int lane = t & 31;
    const int g    = lane >> 2;
    const int tg   = lane & 3;
    const int rg   = wid >> 2;         // rowgroup 0..1 (32 rows each)
    const int h    = wid & 3;          // head
    const int bx = blockIdx.x;
    const int js    = bx & (JS - 1);
    const int itile = bx >> 3;         // JS = 8
    const int i0     = itile * TI;
    const int j0base = js * (NN / JS);

    const int rbase = i0 + rg * 32 + g;    // rows rbase + {0,8,16,24}
    const uint32_t ONES2 = 0x3C003C00u;

    // per-row {E1,E1} / {F1,F1} f16x2 + spread-adj base ptrs
    uint32_t s1E[4], s1F[4];
    const uint32_t* ap[4];
#pragma unroll
    for (int ri = 0; ri < 4; ri++) {
        const int row = rbase + ri * 8;
        uint32_t sv = g_S16[row * NHEAD + h];
        PRMT(s1E[ri], sv, 0x1010);    // {E1, E1}
        PRMT(s1F[ri], sv, 0x3232);    // {F1, F1}
        ap[ri] = g_adjS + ((size_t)row * 128 + (j0base >> 6)) * 4 + tg;
    }

    auto stage = [&](int buf, int j0) {
#pragma unroll
        for (int v = 0; v < 8; v++) {
            int idx = v * 256 + t;
            int row = idx >> 3, u = idx & 7;
            const __half* src = g_WTf16 + (size_t)row * NN + j0 + u * 8;
            uint32_t dst = ab + OFF_B + buf * 32768 + SMEM_SWZ((uint32_t)(row * 128 + u * 16));
            CP_ASYNC16(dst, src);
        }
        if (t < 64) {
            int hh = t >> 4, plane = (t >> 3) & 1, gn = t & 7;
            const __half* src = (plane ? g_F2h : g_E2h) + (size_t)hh * NN + j0 + gn * 8;
            uint32_t dst = ab + OFF_EFS + buf * 1024 + (uint32_t)(hh * 256 + plane * 128 + gn * 16);
            CP_ASYNC16(dst, src);
        }
    };

    stage(0, j0base);
    CP_COMMIT();
    stage(1, j0base + TJ);
    CP_COMMIT();

    float acc[2][8][4];
#pragma unroll
    for (int mt = 0; mt < 2; mt++)
#pragma unroll
        for (int nt = 0; nt < 8; nt++)
#pragma unroll
            for (int q = 0; q < 4; q++) acc[mt][nt][q] = 0.0f;
    float accd[2][4];
#pragma unroll
    for (int mt = 0; mt < 2; mt++)
#pragma unroll
        for (int q = 0; q < 4; q++) accd[mt][q] = 0.0f;

    for (int ch = 0; ch < JCH; ch++) {
        const int buf = ch % 3;
        const int j0  = j0base + ch * TJ;

        // spread adj words for this chunk (4 rows, L2-resident, read once)
        uint32_t aw[4];
#pragma unroll
        for (int ri = 0; ri < 4; ri++) aw[ri] = ap[ri][ch * 4];

        if (ch < JCH - 1) CP_WAIT(1); else CP_WAIT(0);
        __syncthreads();

        if (ch + 2 < JCH) {
            stage((ch + 2) % 3, j0 + 2 * TJ);
            CP_COMMIT();
        }

        const uint32_t Eoff = OFF_EFS + buf * 1024 + (uint32_t)h * 256;
        const uint32_t Bb = ab + OFF_B + buf * 32768;
        const int r_c = lane & 7;
        const int jo2 = ((lane >> 3) & 1) * 8;

#pragma unroll
        for (int sp = 0; sp < 2; sp++) {
#pragma unroll
            for (int k2 = 0; k2 < 2; k2++) {
                const int s = sp * 2 + k2;

                // ---- phase 1: issue ALL loads for this k-step ----
                const uint32_t eb = Eoff + (uint32_t)(s * 8 + tg) * 4;
                uint32_t e01 = *(const uint32_t*)(abp + eb);
                uint32_t e89 = *(const uint32_t*)(abp + eb + 16);
                uint32_t f01 = *(const uint32_t*)(abp + eb + 128);
                uint32_t f89 = *(const uint32_t*)(abp + eb + 144);

                uint32_t bfr[8][2];
#pragma unroll
                for (int nt = 0; nt < 8; nt++) {
                    uint32_t addr = Bb + (uint32_t)(h * 8192)
                        + SMEM_SWZ((uint32_t)((nt * 8 + r_c) * 128
                                              + (sp * 32 + k2 * 16 + jo2) * 2));
                    LDSM2(bfr[nt][0], bfr[nt][1], addr);
                }

                // ---- phase 2: amt chain (executes under load latency) ----
                uint32_t amt[2][4];
#pragma unroll
                for (int ri = 0; ri < 4; ri++) {
                    uint32_t xs = aw[ri] << (3 - s);
                    uint32_t m01, m89;
                    PRMT(m01, xs, 0x9988);
                    PRMT(m89, xs, 0xBBAA);
                    uint32_t t1, t2, w01, w89;
                    HMUL2(t1, s1E[ri], e01);
                    HMUL2(t2, s1F[ri], f01);
                    HMAX2(w01, t1, t2);
                    HMUL2(t1, s1E[ri], e89);
                    HMUL2(t2, s1F[ri], f89);
                    HMAX2(w89, t1, t2);
                    amt[ri >> 1][ri & 1]       = w01 & m01;
                    amt[ri >> 1][(ri & 1) + 2] = w89 & m89;
                }

                // ---- phase 3: MMAs (operands ready) ----
                MMA16816(accd[0], amt[0][0], amt[0][1], amt[0][2], amt[0][3], ONES2, ONES2);
                MMA16816(accd[1], amt[1][0], amt[1][1], amt[1][2], amt[1][3], ONES2, ONES2);
#pragma unroll
                for (int nt = 0; nt < 8; nt++)
#pragma unroll
                    for (int mt = 0; mt < 2; mt++)
                        MMA16816(acc[mt][nt],
                                 amt[mt][0], amt[mt][1], amt[mt][2], amt[mt][3],
                                 bfr[nt][0], bfr[nt][1]);
            }
        }
    }

    // ---- epilogue ----
    if (tg == 0) {
#pragma unroll
        for (int ri = 0; ri < 4; ri++)
            g_denP[((size_t)js * NN + rbase + ri * 8) * NHEAD + h] =
                accd[ri >> 1][(ri & 1) * 2];
    }
#pragma unroll
    for (int mt = 0; mt < 2; mt++) {
        const size_t r0 = (size_t)js * NN + rbase + mt * 16;
#pragma unroll
        for (int nt = 0; nt < 8; nt++) {
            const int c0 = h * 64 + nt * 8 + tg * 2;
            *(float2*)(g_outP + r0 * COLS + c0) =
                make_float2(acc[mt][nt][0], acc[mt][nt][1]);
            *(float2*)(g_outP + (r0 + 8) * COLS + c0) =
                make_float2(acc[mt][nt][2], acc[mt][nt][3]);
        }
    }
}

// ---------------------------------------------------------------------------
// Kernel 3: combine j-split partials
// ---------------------------------------------------------------------------
__global__ __launch_bounds__(256) void k_comb(float* __restrict__ out)
{
    const int idx = blockIdx.x * 256 + threadIdx.x;   // float4 index over NN*64
    const int i  = idx >> 6;
    const int c4 = idx & 63;
    const int h  = c4 >> 4;

    float4 s = make_float4(0.f, 0.f, 0.f, 0.f);
    float d = 0.f;
#pragma unroll
    for (int js = 0; js < JS; js++) {
        float4 p = ((const float4*)g_outP)[((size_t)js * NN + i) * 64 + c4];
        s.x += p.x; s.y += p.y; s.z += p.z; s.w += p.w;
        d += g_denP[((size_t)js * NN + i) * NHEAD + h];
    }
    float inv = 1.0f / d;
    ((float4*)out)[idx] = make_float4(s.x * inv, s.y * inv, s.z * inv, s.w * inv);
}

// ---------------------------------------------------------------------------
extern "C" void kernel_launch(void* const* d_in, const int* in_sizes, int n_in,
                              void* d_out, int out_size)
{
    const float* hmat = (const float*)d_in[0];   // [8192, 256] f32
    const int*   adj  = (const int*)  d_in[1];   // [8192, 8192] i32
    const float* W    = (const float*)d_in[2];   // [4, 256, 64] f32
    const float* a    = (const float*)d_in[3];   // [128, 1] f32
    float* out = (float*)d_out;                  // [8192, 256] f32

    cudaFuncSetAttribute(k_attn, cudaFuncAttributeMaxDynamicSharedMemorySize, SMEM_REQ);

    k_pg    <<<1536, 256>>>(adj, hmat, W);
    k_scores<<<(NN * NHEAD) / 8, 256>>>(a);
    k_attn  <<<(NN / TI) * JS, 256, SMEM_REQ>>>();
    k_comb  <<<(NN * 64) / 256, 256>>>(out);
}

// round 17
// speedup vs baseline: 1.0829x; 1.0032x over previous
#include <cuda_runtime.h>
#include <cuda_fp16.h>
#include <cstdint>

// Problem constants
#define NN       8192
#define IN_DIM   256
#define NHEAD    4
#define HDIM     64
#define COLS     256   // NHEAD*HDIM

// attention tiling
#define TI   64                    // rows per block
#define TJ   64                    // j per chunk (K)
#define JS   8                     // j-splits
#define JCH  ((NN / JS) / TJ)      // 16 chunks per block

// smem byte offsets — 3-deep ring
#define OFF_B     0u               // 3 bufs x 32768 (256 c-rows x 64 j fp16, SW128)
#define OFF_EFS   98304u           // 3 bufs x 1024 ([h][plane][32 u32] E/F fp16 pairs)
#define SMEM_REQ  (101376u + 1024u)

#define SMEM_SWZ(off) ((off) ^ (((off) >> 3) & 0x70u))

// ---------------- PTX helpers ----------------
__device__ __forceinline__ uint32_t smem_u32(const void* p) {
    uint32_t a;
    asm("{ .reg .u64 t; cvta.to.shared.u64 t, %1; cvt.u32.u64 %0, t; }" : "=r"(a) : "l"(p));
    return a;
}
#define PACK2(out, lo, hi) \
    asm("mov.b64 %0, {%1, %2};" : "=l"(out) : "f"(lo), "f"(hi))
#define UNPACK2(lo, hi, in) \
    asm("mov.b64 {%0, %1}, %2;" : "=f"(lo), "=f"(hi) : "l"(in))
#define FMA2(d, a, b, c) \
    asm("fma.rn.f32x2 %0, %1, %2, %3;" : "=l"(d) : "l"(a), "l"(b), "l"(c))
// pack two f32 -> f16x2 (lo in low half)
#define CVT_F16X2(r, lo, hi) \
    asm("cvt.rn.f16x2.f32 %0, %1, %2;" : "=r"(r) : "f"(hi), "f"(lo))
#define HMUL2(d, a, b) \
    asm("mul.rn.f16x2 %0, %1, %2;" : "=r"(d) : "r"(a), "r"(b))
#define HMAX2(d, a, b) \
    asm("max.f16x2 %0, %1, %2;" : "=r"(d) : "r"(a), "r"(b))
#define PRMT(d, a, sel) \
    asm("prmt.b32 %0, %1, %2, %3;" : "=r"(d) : "r"(a), "r"(0u), "n"(sel))

#define CP_ASYNC16(dst, src) \
    asm volatile("cp.async.cg.shared.global [%0], [%1], 16;" :: "r"(dst), "l"(src))
#define CP_COMMIT() asm volatile("cp.async.commit_group;" ::: "memory")
#define CP_WAIT(n)  asm volatile("cp.async.wait_group %0;" :: "n"(n) : "memory")

#define LDSM2(r0, r1, addr) \
    asm volatile("ldmatrix.sync.aligned.m8n8.x2.shared.b16 {%0,%1}, [%2];" \
        : "=r"(r0), "=r"(r1) : "r"(addr))

#define MMA16816(d, a0, a1, a2, a3, b0, b1) \
    asm volatile("mma.sync.aligned.m16n8k16.row.col.f32.f16.f16.f32 " \
        "{%0,%1,%2,%3}, {%4,%5,%6,%7}, {%8,%9}, {%0,%1,%2,%3};" \
        : "+f"((d)[0]), "+f"((d)[1]), "+f"((d)[2]), "+f"((d)[3]) \
        : "r"(a0), "r"(a1), "r"(a2), "r"(a3), "r"(b0), "r"(b1))

// ---------------- scratch globals ----------------
__device__ float    g_Wht[NN * COLS];            // Wh fp32 [n][c]
__device__ __half   g_WTf16[COLS * NN];          // Wh^T fp16 [c][j]  (4 MB)
__device__ uint32_t g_S16[NN * NHEAD];           // {E1 fp16 low, F1 fp16 high}
__device__ __half   g_E2h[NHEAD * NN];           // e^{s2} fp16, [h][n]
__device__ __half   g_F2h[NHEAD * NN];           // e^{.2 s2} fp16, [h][n]
__device__ uint32_t g_adjS[(size_t)NN * 128 * 4];    // spread bitmask, 16 MB
__device__ float    g_outP[(size_t)JS * NN * COLS];  // 64 MB
__device__ float    g_denP[(size_t)JS * NN * NHEAD];

// ---------------------------------------------------------------------------
// Kernel A: fused pack + gemm + scores. grid = 1536. bx%3==0 -> gemm role
// (512 blocks, includes per-row score/exp epilogue); else -> pack (1024).
// ---------------------------------------------------------------------------
__global__ __launch_bounds__(256) void k_pg(const int* __restrict__ adj,
                                            const float* __restrict__ hmat,
                                            const float* __restrict__ W,
                                            const float* __restrict__ a)
{
    __shared__ __align__(16) float hsT[IN_DIM][18];
    const int bx = blockIdx.x;
    const int t  = threadIdx.x;

    if (bx % 3 != 0) {
        // ---- pack role: spread bitmask ----
        const int pack_idx = bx - bx / 3 - 1;       // 0..1023
        const int row  = pack_idx * 8 + (t >> 5);
        const int lane = t & 31;
        const int* rp = adj + (size_t)row * NN;
        uint32_t* op = g_adjS + (size_t)row * 512;
#pragma unroll 2
        for (int c = 0; c < 128; c++) {
            int v0 = rp[c * 64 + lane];
            int v1 = rp[c * 64 + 32 + lane];
            uint32_t lo = __ballot_sync(0xFFFFFFFFu, v0 != 0);
            uint32_t hi = __ballot_sync(0xFFFFFFFFu, v1 != 0);
            if (lane < 4) {
                uint32_t l = lo >> (lane * 2);
                uint32_t hh = hi >> (lane * 2);
                uint32_t o = 0;
                o |= (l & 0x1u) << 4;          // s0 t0 -> 4
                o |= (l & 0x2u) << 11;         // s0 t1 -> 12
                o |= (l & 0x100u) << 12;       // s0 t2 -> 20
                o |= (l & 0x200u) << 19;       // s0 t3 -> 28
                o |= (l >> 11) & 0x20u;        // s1 t0 -> 5
                o |= (l & 0x20000u) >> 4;      // s1 t1 -> 13
                o |= (l & 0x1000000u) >> 3;    // s1 t2 -> 21
                o |= (l & 0x2000000u) << 4;    // s1 t3 -> 29
                o |= (hh & 0x1u) << 6;         // s2 t0 -> 6
                o |= (hh & 0x2u) << 13;        // s2 t1 -> 14
                o |= (hh & 0x100u) << 14;      // s2 t2 -> 22
                o |= (hh & 0x200u) << 21;      // s2 t3 -> 30
                o |= (hh >> 9) & 0x80u;        // s3 t0 -> 7
                o |= (hh & 0x20000u) >> 2;     // s3 t1 -> 15
                o |= (hh & 0x1000000u) >> 1;   // s3 t2 -> 23
                o |= (hh & 0x2000000u) << 6;   // s3 t3 -> 31
                op[c * 4 + lane] = o;
            }
        }
        return;
    }

    // ---- gemm role: Wh = h @ W, emit fp32 Wh, fp16 Wh^T, and scores ----
    const int n0 = (bx / 3) * 16;

    for (int q = t; q < 1024; q += 256) {
        int row = q >> 6, kq = q & 63;
        float4 v = *(const float4*)(hmat + (n0 + row) * IN_DIM + kq * 4);
        hsT[kq * 4 + 0][row] = v.x;
        hsT[kq * 4 + 1][row] = v.y;
        hsT[kq * 4 + 2][row] = v.z;
        hsT[kq * 4 + 3][row] = v.w;
    }
    __syncthreads();

    const int c = t;
    const int head = c >> 6, d = c & 63;
    const float* Wp = W + head * (IN_DIM * HDIM) + d;

    unsigned long long acc[8];
#pragma unroll
    for (int rp = 0; rp < 8; rp++) acc[rp] = 0ull;

#pragma unroll 4
    for (int k = 0; k < IN_DIM; k++) {
        float wv = Wp[k * HDIM];
        unsigned long long ws;
        PACK2(ws, wv, wv);
#pragma unroll
        for (int rp = 0; rp < 8; rp++) {
            unsigned long long hv = *(const unsigned long long*)&hsT[k][rp * 2];
            FMA2(acc[rp], hv, ws, acc[rp]);
        }
    }

    float val[16];
#pragma unroll
    for (int rp = 0; rp < 8; rp++) {
        UNPACK2(val[2 * rp], val[2 * rp + 1], acc[rp]);
        g_Wht[(n0 + 2 * rp + 0) * COLS + c] = val[2 * rp];
        g_Wht[(n0 + 2 * rp + 1) * COLS + c] = val[2 * rp + 1];
    }
    uint32_t hp[8];
#pragma unroll
    for (int q = 0; q < 8; q++) CVT_F16X2(hp[q], val[2 * q], val[2 * q + 1]);
    uint4* pd = (uint4*)(g_WTf16 + (size_t)c * NN + n0);
    pd[0] = make_uint4(hp[0], hp[1], hp[2], hp[3]);
    pd[1] = make_uint4(hp[4], hp[5], hp[6], hp[7]);

    // ---- scores epilogue: reuse hsT as [row][c] (stride 260) scratch ----
    float* sc = (float*)hsT;
    __syncthreads();   // mainloop done with hsT
#pragma unroll
    for (int r = 0; r < 16; r++) sc[r * 260 + c] = val[r];
    __syncthreads();

    if (t < 64) {
        const int r = t >> 2, hh = t & 3;
        const float* vp = sc + r * 260 + hh * 64;
        float p1 = 0.0f, p2 = 0.0f;
#pragma unroll 8
        for (int dd = 0; dd < 64; dd++) {
            float v = vp[dd];
            p1 += v * a[dd];
            p2 += v * a[64 + dd];
        }
        const int n = n0 + r;
        __half e1 = __float2half(expf(p1));
        __half f1 = __float2half(expf(0.2f * p1));
        uint32_t e1b, f1b;
        memcpy(&e1b, &e1, 2); e1b &= 0xFFFFu;
        memcpy(&f1b, &f1, 2); f1b &= 0xFFFFu;
        g_S16[n * NHEAD + hh] = e1b | (f1b << 16);
        g_E2h[hh * NN + n] = __float2half(expf(p2));
        g_F2h[hh * NN + n] = __float2half(expf(0.2f * p2));
    }
}

// ---------------------------------------------------------------------------
// Kernel 2: HMMA attention aggregation. grid = (NN/TI)*JS = 1024, 256 thr,
// 2 blocks/SM. Warp = 32 rows x 1 head. fp16-native weight phase.
// Per k-step: ALL loads (LDS + 8x LDSM2) issued first, amt chain computed
// under their latency, MMAs last with both operands ready.
// ---------------------------------------------------------------------------
__global__ __launch_bounds__(256, 2) void k_attn()
{
    extern __shared__ __align__(16) char dsm[];
    const uint32_t sb = smem_u32(dsm);
    const uint32_t ab = (sb + 1023u) & ~1023u;
    char* abp = dsm + (ab - sb);

    const int t    = threadIdx.x;
    const int wid  = t >> 5;
    const int lane = t & 31;
    const int g    = lane >> 2;
    const int tg   = lane & 3;
    const int rg   = wid >> 2;         // rowgroup 0..1 (32 rows each)
    const int h    = wid & 3;          // head
    const int bx = blockIdx.x;
    const int js    = bx & (JS - 1);
    const int itile = bx >> 3;         // JS = 8
    const int i0     = itile * TI;
    const int j0base = js * (NN / JS);

    const int rbase = i0 + rg * 32 + g;    // rows rbase + {0,8,16,24}
    const uint32_t ONES2 = 0x3C003C00u;

    // per-row {E1,E1} / {F1,F1} f16x2 + spread-adj base ptrs
    uint32_t s1E[4], s1F[4];
    const uint32_t* ap[4];
#pragma unroll
    for (int ri = 0; ri < 4; ri++) {
        const int row = rbase + ri * 8;
        uint32_t sv = g_S16[row * NHEAD + h];
        PRMT(s1E[ri], sv, 0x1010);    // {E1, E1}
        PRMT(s1F[ri], sv, 0x3232);    // {F1, F1}
        ap[ri] = g_adjS + ((size_t)row * 128 + (j0base >> 6)) * 4 + tg;
    }

    auto stage = [&](int buf, int j0) {
#pragma unroll
        for (int v = 0; v < 8; v++) {
            int idx = v * 256 + t;
            int row = idx >> 3, u = idx & 7;
            const __half* src = g_WTf16 + (size_t)row * NN + j0 + u * 8;
            uint32_t dst = ab + OFF_B + buf * 32768 + SMEM_SWZ((uint32_t)(row * 128 + u * 16));
            CP_ASYNC16(dst, src);
        }
        if (t < 64) {
            int hh = t >> 4, plane = (t >> 3) & 1, gn = t & 7;
            const __half* src = (plane ? g_F2h : g_E2h) + (size_t)hh * NN + j0 + gn * 8;
            uint32_t dst = ab + OFF_EFS + buf * 1024 + (uint32_t)(hh * 256 + plane * 128 + gn * 16);
            CP_ASYNC16(dst, src);
        }
    };

    stage(0, j0base);
    CP_COMMIT();
    stage(1, j0base + TJ);
    CP_COMMIT();

    float acc[2][8][4];
#pragma unroll
    for (int mt = 0; mt < 2; mt++)
#pragma unroll
        for (int nt = 0; nt < 8; nt++)
#pragma unroll
            for (int q = 0; q < 4; q++) acc[mt][nt][q] = 0.0f;
    float accd[2][4];
#pragma unroll
    for (int mt = 0; mt < 2; mt++)
#pragma unroll
        for (int q = 0; q < 4; q++) accd[mt][q] = 0.0f;

    for (int ch = 0; ch < JCH; ch++) {
        const int buf = ch % 3;
        const int j0  = j0base + ch * TJ;

        // spread adj words for this chunk (4 rows, L2-resident, read once)
        uint32_t aw[4];
#pragma unroll
        for (int ri = 0; ri < 4; ri++) aw[ri] = ap[ri][ch * 4];

        if (ch < JCH - 1) CP_WAIT(1); else CP_WAIT(0);
        __syncthreads();

        if (ch + 2 < JCH) {
            stage((ch + 2) % 3, j0 + 2 * TJ);
            CP_COMMIT();
        }

        const uint32_t Eoff = OFF_EFS + buf * 1024 + (uint32_t)h * 256;
        const uint32_t Bb = ab + OFF_B + buf * 32768;
        const int r_c = lane & 7;
        const int jo2 = ((lane >> 3) & 1) * 8;

#pragma unroll
        for (int sp = 0; sp < 2; sp++) {
#pragma unroll
            for (int k2 = 0; k2 < 2; k2++) {
                const int s = sp * 2 + k2;

                // ---- phase 1: issue ALL loads for this k-step ----
                const uint32_t eb = Eoff + (uint32_t)(s * 8 + tg) * 4;
                uint32_t e01 = *(const uint32_t*)(abp + eb);
                uint32_t e89 = *(const uint32_t*)(abp + eb + 16);
                uint32_t f01 = *(const uint32_t*)(abp + eb + 128);
                uint32_t f89 = *(const uint32_t*)(abp + eb + 144);

                uint32_t bfr[8][2];
#pragma unroll
                for (int nt = 0; nt < 8; nt++) {
                    uint32_t addr = Bb + (uint32_t)(h * 8192)
                        + SMEM_SWZ((uint32_t)((nt * 8 + r_c) * 128
                                              + (sp * 32 + k2 * 16 + jo2) * 2));
                    LDSM2(bfr[nt][0], bfr[nt][1], addr);
                }

                // ---- phase 2: amt chain (executes under load latency) ----
                uint32_t amt[2][4];
#pragma unroll
                for (int ri = 0; ri < 4; ri++) {
                    uint32_t xs = aw[ri] << (3 - s);
                    uint32_t m01, m89;
                    PRMT(m01, xs, 0x9988);
                    PRMT(m89, xs, 0xBBAA);
                    uint32_t t1, t2, w01, w89;
                    HMUL2(t1, s1E[ri], e01);
                    HMUL2(t2, s1F[ri], f01);
                    HMAX2(w01, t1, t2);
                    HMUL2(t1, s1E[ri], e89);
                    HMUL2(t2, s1F[ri], f89);
                    HMAX2(w89, t1, t2);
                    amt[ri >> 1][ri & 1]       = w01 & m01;
                    amt[ri >> 1][(ri & 1) + 2] = w89 & m89;
                }

                // ---- phase 3: MMAs (operands ready) ----
                MMA16816(accd[0], amt[0][0], amt[0][1], amt[0][2], amt[0][3], ONES2, ONES2);
                MMA16816(accd[1], amt[1][0], amt[1][1], amt[1][2], amt[1][3], ONES2, ONES2);
#pragma unroll
                for (int nt = 0; nt < 8; nt++)
#pragma unroll
                    for (int mt = 0; mt < 2; mt++)
                        MMA16816(acc[mt][nt],
                                 amt[mt][0], amt[mt][1], amt[mt][2], amt[mt][3],
                                 bfr[nt][0], bfr[nt][1]);
            }
        }
    }

    // ---- epilogue ----
    if (tg == 0) {
#pragma unroll
        for (int ri = 0; ri < 4; ri++)
            g_denP[((size_t)js * NN + rbase + ri * 8) * NHEAD + h] =
                accd[ri >> 1][(ri & 1) * 2];
    }
#pragma unroll
    for (int mt = 0; mt < 2; mt++) {
        const size_t r0 = (size_t)js * NN + rbase + mt * 16;
#pragma unroll
        for (int nt = 0; nt < 8; nt++) {
            const int c0 = h * 64 + nt * 8 + tg * 2;
            *(float2*)(g_outP + r0 * COLS + c0) =
                make_float2(acc[mt][nt][0], acc[mt][nt][1]);
            *(float2*)(g_outP + (r0 + 8) * COLS + c0) =
                make_float2(acc[mt][nt][2], acc[mt][nt][3]);
        }
    }
}

// ---------------------------------------------------------------------------
// Kernel 3: combine j-split partials
// ---------------------------------------------------------------------------
__global__ __launch_bounds__(256) void k_comb(float* __restrict__ out)
{
    const int idx = blockIdx.x * 256 + threadIdx.x;   // float4 index over NN*64
    const int i  = idx >> 6;
    const int c4 = idx & 63;
    const int h  = c4 >> 4;

    float4 s = make_float4(0.f, 0.f, 0.f, 0.f);
    float d = 0.f;
#pragma unroll
    for (int js = 0; js < JS; js++) {
        float4 p = ((const float4*)g_outP)[((size_t)js * NN + i) * 64 + c4];
        s.x += p.x; s.y += p.y; s.z += p.z; s.w += p.w;
        d += g_denP[((size_t)js * NN + i) * NHEAD + h];
    }
    float inv = 1.0f / d;
    ((float4*)out)[idx] = make_float4(s.x * inv, s.y * inv, s.z * inv, s.w * inv);
}

// ---------------------------------------------------------------------------
extern "C" void kernel_launch(void* const* d_in, const int* in_sizes, int n_in,
                              void* d_out, int out_size)
{
    const float* hmat = (const float*)d_in[0];   // [8192, 256] f32
    const int*   adj  = (const int*)  d_in[1];   // [8192, 8192] i32
    const float* W    = (const float*)d_in[2];   // [4, 256, 64] f32
    const float* a    = (const float*)d_in[3];   // [128, 1] f32
    float* out = (float*)d_out;                  // [8192, 256] f32

    cudaFuncSetAttribute(k_attn, cudaFuncAttributeMaxDynamicSharedMemorySize, SMEM_REQ);

    k_pg    <<<1536, 256>>>(adj, hmat, W, a);
    k_attn  <<<(NN / TI) * JS, 256, SMEM_REQ>>>();
    k_comb  <<<(NN * 64) / 256, 256>>>(out);
}